// round 15
// baseline (speedup 1.0000x reference)
#include <cuda_runtime.h>
#include <cuda_bf16.h>
#include <stdint.h>

#define M_SIZE 4096
#define NMODES 128
#define BATCH  32
#define CH     256
#define NROWS  (BATCH*CH)   // 8192
#define NC     (2*NMODES)   // 256

// ---------------- device scratch (allocation-free globals) ----------------
__device__ __nv_bfloat16 g_basis_h[(size_t)M_SIZE*NC];   // [t][c]  (inv B)
__device__ __nv_bfloat16 g_basis_l[(size_t)M_SIZE*NC];
__device__ __nv_bfloat16 g_basisT_h[(size_t)NC*M_SIZE];  // [c][t]  (fwd B)
__device__ __nv_bfloat16 g_basisT_l[(size_t)NC*M_SIZE];
__device__ __nv_bfloat16 g_xT_h[(size_t)NC*NROWS];       // xft planes [c][row]
__device__ __nv_bfloat16 g_xT_l[(size_t)NC*NROWS];
// weight planes [m][o][i] bf16 hi/lo
__device__ __nv_bfloat16 gWre_h[(size_t)NMODES*CH*CH], gWre_l[(size_t)NMODES*CH*CH];
__device__ __nv_bfloat16 gWim_h[(size_t)NMODES*CH*CH], gWim_l[(size_t)NMODES*CH*CH];
__device__ __nv_bfloat16 g_oft_h[(size_t)NROWS*NC];      // [row][c] scaled
__device__ __nv_bfloat16 g_oft_l[(size_t)NROWS*NC];

// ---------------- helpers ----------------
__device__ __forceinline__ uint32_t smem_u32(const void* p) {
    uint32_t a;
    asm("{ .reg .u64 t; cvta.to.shared.u64 t, %1; cvt.u32.u64 %0, t; }" : "=r"(a) : "l"(p));
    return a;
}
#define SW(o) ((uint32_t)(o) ^ ((((uint32_t)(o)) >> 3) & 0x70))

#define CP16(d, s)  asm volatile("cp.async.cg.shared.global [%0], [%1], 16;" :: "r"(d), "l"(s))
#define CP_COMMIT() asm volatile("cp.async.commit_group;")
#define CP_WAIT0()  asm volatile("cp.async.wait_group 0;")

#define LDSM4(R, addr) \
    asm volatile("ldmatrix.sync.aligned.m8n8.x4.shared.b16 {%0,%1,%2,%3}, [%4];" \
        : "=r"((R)[0]), "=r"((R)[1]), "=r"((R)[2]), "=r"((R)[3]) : "r"(addr))

#define MMA4(C, A, b0, b1) \
    asm volatile("mma.sync.aligned.m16n8k16.row.col.f32.bf16.bf16.f32 " \
        "{%0,%1,%2,%3},{%4,%5,%6,%7},{%8,%9},{%0,%1,%2,%3};" \
        : "+f"((C)[0]), "+f"((C)[1]), "+f"((C)[2]), "+f"((C)[3]) \
        : "r"((A)[0]), "r"((A)[1]), "r"((A)[2]), "r"((A)[3]), "r"(b0), "r"(b1))

__device__ __forceinline__ void split_bf16(float v, __nv_bfloat16& h, __nv_bfloat16& l) {
    h = __float2bfloat16(v);
    l = __float2bfloat16(v - __bfloat162float(h));
}
__device__ __forceinline__ uint2 pack4(__nv_bfloat16 a, __nv_bfloat16 b,
                                       __nv_bfloat16 c, __nv_bfloat16 d) {
    __nv_bfloat162 p = __halves2bfloat162(a, b), q = __halves2bfloat162(c, d);
    return make_uint2(*(uint32_t*)&p, *(uint32_t*)&q);
}

// ---------------------------------------------------------------------------
// Fused prep: basis_a (blocks 0..2047), basis_b (2048..4095), wtransp (4096..8191)
// ---------------------------------------------------------------------------
__global__ void __launch_bounds__(256) k_prep(const float2* __restrict__ w2) {
    __shared__ float2 s[64][33];
    const int b = blockIdx.x;
    const int tid = threadIdx.x;
    if (b < 2048) {
        int idx = b * 256 + tid;
        int t = idx >> 7, m = idx & 127;
        int r = (t * m) & (M_SIZE - 1);
        float sn, cs;
        sincospif((float)r * (1.0f / 2048.0f), &sn, &cs);
        __nv_bfloat16 ch, cl, sh, sl;
        split_bf16(cs, ch, cl); split_bf16(-sn, sh, sl);
        size_t base = (size_t)t * NC + 2 * m;
        *(__nv_bfloat162*)&g_basis_h[base] = __halves2bfloat162(ch, sh);
        *(__nv_bfloat162*)&g_basis_l[base] = __halves2bfloat162(cl, sl);
    } else if (b < 4096) {
        int idx = (b - 2048) * 256 + tid;
        int m = idx >> 12, t = idx & 4095;
        int r = (t * m) & (M_SIZE - 1);
        float sn, cs;
        sincospif((float)r * (1.0f / 2048.0f), &sn, &cs);
        __nv_bfloat16 ch, cl, sh, sl;
        split_bf16(cs, ch, cl); split_bf16(-sn, sh, sl);
        g_basisT_h[(size_t)(2*m)   * M_SIZE + t] = ch;
        g_basisT_h[(size_t)(2*m+1) * M_SIZE + t] = sh;
        g_basisT_l[(size_t)(2*m)   * M_SIZE + t] = cl;
        g_basisT_l[(size_t)(2*m+1) * M_SIZE + t] = sl;
    } else {
        int lb = b - 4096;
        const int i0 = (lb & 3) * 64;
        const int m0 = ((lb >> 2) & 3) * 32;
        const int o  = lb >> 4;
#pragma unroll
        for (int j = 0; j < 8; j++) {
            int f = tid + j * 256;
            int ii = f >> 5, ml = f & 31;
            s[ii][ml] = w2[((size_t)o * CH + i0 + ii) * NMODES + m0 + ml];
        }
        __syncthreads();
#pragma unroll
        for (int j = 0; j < 2; j++) {
            int f = tid + j * 256;
            int ml = f >> 4, ig = (f & 15) * 4;
            float2 v0 = s[ig][ml], v1 = s[ig+1][ml], v2 = s[ig+2][ml], v3 = s[ig+3][ml];
            size_t dst = ((size_t)(m0 + ml) * CH + o) * CH + i0 + ig;
            __nv_bfloat16 h0,l0,h1,l1,h2,l2,h3,l3;
            split_bf16(v0.x,h0,l0); split_bf16(v1.x,h1,l1);
            split_bf16(v2.x,h2,l2); split_bf16(v3.x,h3,l3);
            *(uint2*)&gWre_h[dst] = pack4(h0,h1,h2,h3);
            *(uint2*)&gWre_l[dst] = pack4(l0,l1,l2,l3);
            split_bf16(v0.y,h0,l0); split_bf16(v1.y,h1,l1);
            split_bf16(v2.y,h2,l2); split_bf16(v3.y,h3,l3);
            *(uint2*)&gWim_h[dst] = pack4(h0,h1,h2,h3);
            *(uint2*)&gWim_l[dst] = pack4(l0,l1,l2,l3);
        }
    }
}

// ---------------------------------------------------------------------------
// Forward DFT (R13-proven): xT[c][row] = sum_k x[row][k]*basisT[c][k]
// 256 threads, 8 warps 2x4 (warp 64x32), block 128x128, K-chunk 64.
// ---------------------------------------------------------------------------
#define F_AH 0
#define F_AL 16384
#define F_BH 32768
#define F_BL 49152
#define FBUF 65536
#define SMEM_FWD (2*FBUF)   // 128KB, 1 CTA/SM

__global__ void __launch_bounds__(256, 1) k_fwd(const float* __restrict__ x) {
    extern __shared__ char sm[];
    uint32_t sb = smem_u32(sm);
    const int tid = threadIdx.x, lane = tid & 31, wid = tid >> 5;
    const int wm = wid & 1, wn = wid >> 1;
    const int row0 = blockIdx.x * 128;
    const int c0   = blockIdx.y * 128;

    uint32_t offA[4], offB[2];
#pragma unroll
    for (int mf = 0; mf < 4; mf++)
        offA[mf] = (wm*64 + mf*16 + (lane & 15)) * 128 + (lane >> 4) * 16;
#pragma unroll
    for (int p = 0; p < 2; p++)
        offB[p] = (wn*32 + p*16 + ((lane >> 4) << 3) + (lane & 7)) * 128
                + ((lane >> 3) & 1) * 16;

    float acc[4][4][4];
#pragma unroll
    for (int i = 0; i < 4; i++)
#pragma unroll
        for (int j = 0; j < 4; j++)
#pragma unroll
            for (int q = 0; q < 4; q++) acc[i][j][q] = 0.0f;

    // ---- preload chunk 0 ----
    {
        const int k0 = 0;
#pragma unroll
        for (int j = 0; j < 8; j++) {
            int f = tid + j * 256;
            int plane = f >> 10, r = (f >> 3) & 127, cb = f & 7;
            const __nv_bfloat16* src = (plane ? g_basisT_l : g_basisT_h)
                                     + (size_t)(c0 + r) * M_SIZE + k0 + cb * 8;
            CP16(sb + F_BH + plane * 16384 + SW(r * 128 + cb * 16), src);
        }
        CP_COMMIT();
#pragma unroll
        for (int it = 0; it < 8; it++) {
            int f = tid + it * 256;
            int r = f >> 4, q = f & 15;
            float4 v = *(const float4*)&x[(size_t)(row0 + r) * M_SIZE + k0 + q * 4];
            __nv_bfloat16 h0,l0,h1,l1,h2,l2,h3,l3;
            split_bf16(v.x,h0,l0); split_bf16(v.y,h1,l1);
            split_bf16(v.z,h2,l2); split_bf16(v.w,h3,l3);
            uint32_t off = SW(r * 128 + q * 8);
            *(uint2*)(sm + F_AH + off) = pack4(h0,h1,h2,h3);
            *(uint2*)(sm + F_AL + off) = pack4(l0,l1,l2,l3);
        }
        CP_WAIT0();
    }
    __syncthreads();

    const int NCHUNK = M_SIZE / 64;
    for (int cc = 0; cc < NCHUNK; cc++) {
        uint32_t bb  = sb + (cc & 1) * FBUF;
        char*    nbp = sm + ((cc + 1) & 1) * FBUF;
        uint32_t nbb = sb + ((cc + 1) & 1) * FBUF;
        bool pf = (cc + 1 < NCHUNK);
        float4 va[8];
        int rpf[8], qpf[8];
        if (pf) {
            const int k1 = (cc + 1) * 64;
#pragma unroll
            for (int j = 0; j < 8; j++) {
                int f = tid + j * 256;
                int plane = f >> 10, r = (f >> 3) & 127, cb = f & 7;
                const __nv_bfloat16* src = (plane ? g_basisT_l : g_basisT_h)
                                         + (size_t)(c0 + r) * M_SIZE + k1 + cb * 8;
                CP16(nbb + F_BH + plane * 16384 + SW(r * 128 + cb * 16), src);
            }
            CP_COMMIT();
#pragma unroll
            for (int it = 0; it < 8; it++) {
                int f = tid + it * 256;
                rpf[it] = f >> 4; qpf[it] = f & 15;
                va[it] = *(const float4*)&x[(size_t)(row0 + rpf[it]) * M_SIZE + k1 + qpf[it] * 4];
            }
        }
#pragma unroll
        for (int ks = 0; ks < 4; ks++) {
            uint32_t Af[4][4], Bh[2][4], Bo[2][4];
#pragma unroll
            for (int mf = 0; mf < 4; mf++) LDSM4(Af[mf], bb + F_AH + SW(offA[mf] + ks * 32));
#pragma unroll
            for (int p = 0; p < 2; p++)    LDSM4(Bh[p],  bb + F_BH + SW(offB[p] + ks * 32));
#pragma unroll
            for (int mf = 0; mf < 4; mf++)
#pragma unroll
                for (int nf = 0; nf < 4; nf++)
                    MMA4(acc[mf][nf], Af[mf], Bh[nf>>1][(nf&1)*2], Bh[nf>>1][(nf&1)*2+1]);
#pragma unroll
            for (int p = 0; p < 2; p++)    LDSM4(Bo[p],  bb + F_BL + SW(offB[p] + ks * 32));
#pragma unroll
            for (int mf = 0; mf < 4; mf++)
#pragma unroll
                for (int nf = 0; nf < 4; nf++)
                    MMA4(acc[mf][nf], Af[mf], Bo[nf>>1][(nf&1)*2], Bo[nf>>1][(nf&1)*2+1]);
#pragma unroll
            for (int mf = 0; mf < 4; mf++) LDSM4(Af[mf], bb + F_AL + SW(offA[mf] + ks * 32));
#pragma unroll
            for (int mf = 0; mf < 4; mf++)
#pragma unroll
                for (int nf = 0; nf < 4; nf++)
                    MMA4(acc[mf][nf], Af[mf], Bh[nf>>1][(nf&1)*2], Bh[nf>>1][(nf&1)*2+1]);
        }
        if (pf) {
#pragma unroll
            for (int it = 0; it < 8; it++) {
                float4 v = va[it];
                __nv_bfloat16 h0,l0,h1,l1,h2,l2,h3,l3;
                split_bf16(v.x,h0,l0); split_bf16(v.y,h1,l1);
                split_bf16(v.z,h2,l2); split_bf16(v.w,h3,l3);
                uint32_t off = SW(rpf[it] * 128 + qpf[it] * 8);
                *(uint2*)(nbp + F_AH + off) = pack4(h0,h1,h2,h3);
                *(uint2*)(nbp + F_AL + off) = pack4(l0,l1,l2,l3);
            }
        }
        CP_WAIT0();
        __syncthreads();
    }

    // ---- epilogue: stage accs in smem, coalesced bf16 plane writes ----
    float* stage = (float*)sm;
#pragma unroll
    for (int mf = 0; mf < 4; mf++) {
        int lr = wm*64 + mf*16 + (lane >> 2);
#pragma unroll
        for (int nf = 0; nf < 4; nf++) {
            int lc = wn*32 + nf*8 + (lane & 3) * 2;
#pragma unroll
            for (int q = 0; q < 4; q++)
                stage[(lc + (q & 1)) * 132 + lr + (q >> 1) * 8] = acc[mf][nf][q];
        }
    }
    __syncthreads();
    {
        const int c  = tid >> 1;
        const int rh = tid & 1;
        const float* srow = stage + c * 132 + rh * 64;
        __nv_bfloat16* dh = &g_xT_h[(size_t)(c0 + c) * NROWS + row0 + rh * 64];
        __nv_bfloat16* dl = &g_xT_l[(size_t)(c0 + c) * NROWS + row0 + rh * 64];
#pragma unroll
        for (int i = 0; i < 64; i += 4) {
            __nv_bfloat16 h0,l0,h1,l1,h2,l2,h3,l3;
            split_bf16(srow[i],   h0,l0); split_bf16(srow[i+1], h1,l1);
            split_bf16(srow[i+2], h2,l2); split_bf16(srow[i+3], h3,l3);
            *(uint2*)&dh[i] = pack4(h0,h1,h2,h3);
            *(uint2*)&dl[i] = pack4(l0,l1,l2,l3);
        }
    }
}

// ---------------------------------------------------------------------------
// MMA mode mixing (R9/R11-proven). CTA = (mode m, 64-wide o slice).
// ---------------------------------------------------------------------------
#define MX_REH 0
#define MX_REL 16384
#define MX_IMH 32768
#define MX_IML 49152
#define MW_BASE 65536
#define SMEM_MIX (MW_BASE + 32768)   // 96KB

__global__ void __launch_bounds__(256, 2) k_mixmma() {
    extern __shared__ char sm[];
    uint32_t sb = smem_u32(sm);
    const int tid = threadIdx.x, lane = tid & 31, wid = tid >> 5;
    const int wg = wid >> 2, wn = wid & 3;
    const int m  = blockIdx.x;
    const int o0 = blockIdx.y * 64;

#define MIX_LOADW(kk) do {                                                        \
    _Pragma("unroll")                                                             \
    for (int j = 0; j < 8; j++) {                                                 \
        int f = tid + j * 256;                                                    \
        int p = f >> 9, r = (f >> 3) & 63, cb = f & 7;                            \
        const __nv_bfloat16* src = (p == 0) ? gWre_h : (p == 1) ? gWre_l          \
                                 : (p == 2) ? gWim_h : gWim_l;                    \
        CP16(sb + MW_BASE + p * 8192 + SW(r * 128 + cb * 16),                     \
             src + ((size_t)m * CH + o0 + r) * CH + (kk) + cb * 8);               \
    }                                                                             \
    CP_COMMIT();                                                                  \
} while (0)

    {
        const __nv_bfloat16* srcs[4] = {
            g_xT_h + (size_t)(2 * m)     * NROWS,
            g_xT_l + (size_t)(2 * m)     * NROWS,
            g_xT_h + (size_t)(2 * m + 1) * NROWS,
            g_xT_l + (size_t)(2 * m + 1) * NROWS };
#pragma unroll
        for (int j = 0; j < 16; j++) {
            int f = tid + j * 256;
            int p = f >> 10, rem = f & 1023;
            int b = rem >> 5, cb32 = rem & 31;
            int chunk = cb32 >> 3, cb = cb32 & 7;
            CP16(sb + p * 16384 + chunk * 4096 + SW(b * 128 + cb * 16),
                 srcs[p] + (size_t)b * CH + cb32 * 8);
        }
        MIX_LOADW(0);
        CP_WAIT0();
    }
    __syncthreads();

    uint32_t offA[2], offB;
#pragma unroll
    for (int mf = 0; mf < 2; mf++)
        offA[mf] = (mf*16 + (lane & 15)) * 128 + (lane >> 4) * 16;
    offB = (wn*16 + ((lane >> 4) << 3) + (lane & 7)) * 128 + ((lane >> 3) & 1) * 16;

    const uint32_t b1 = wg ? 16384u : 0u;
    const uint32_t b2 = wg ? 0u : 16384u;

    float acc1[2][2][4], acc2[2][2][4];
#pragma unroll
    for (int i = 0; i < 2; i++)
#pragma unroll
        for (int j = 0; j < 2; j++)
#pragma unroll
            for (int q = 0; q < 4; q++) { acc1[i][j][q] = 0.0f; acc2[i][j][q] = 0.0f; }

    for (int cc = 0; cc < 4; cc++) {
        uint32_t wb = sb + MW_BASE;
#pragma unroll
        for (int ks = 0; ks < 4; ks++) {
#pragma unroll
            for (int combo = 0; combo < 2; combo++) {
                uint32_t ah = sb + (combo ? MX_IMH : MX_REH) + cc * 4096;
                uint32_t al = sb + (combo ? MX_IML : MX_REL) + cc * 4096;
                uint32_t bbx = wb + (combo ? b2 : b1);
                float (*acc)[2][4] = combo ? acc2 : acc1;
                uint32_t Ah[2][4], Al[2][4], Bh[4], Bl[4];
#pragma unroll
                for (int mf = 0; mf < 2; mf++) {
                    LDSM4(Ah[mf], ah + SW(offA[mf] + ks * 32));
                    LDSM4(Al[mf], al + SW(offA[mf] + ks * 32));
                }
                LDSM4(Bh, bbx + SW(offB + ks * 32));
                LDSM4(Bl, bbx + 8192 + SW(offB + ks * 32));
#pragma unroll
                for (int mf = 0; mf < 2; mf++)
#pragma unroll
                    for (int nf = 0; nf < 2; nf++) {
                        MMA4(acc[mf][nf], Ah[mf], Bh[nf*2], Bh[nf*2+1]);
                        MMA4(acc[mf][nf], Al[mf], Bh[nf*2], Bh[nf*2+1]);
                        MMA4(acc[mf][nf], Ah[mf], Bl[nf*2], Bl[nf*2+1]);
                    }
            }
        }
        __syncthreads();
        if (cc + 1 < 4) {
            MIX_LOADW((cc + 1) * 64);
            CP_WAIT0();
            __syncthreads();
        }
    }
#undef MIX_LOADW

    const float sgn = wg ? 1.0f : -1.0f;
    const float sc = (m == 0 ? 1.0f : 2.0f) * (1.0f / (float)M_SIZE);
    const int cidx = 2 * m + wg;
#pragma unroll
    for (int mf = 0; mf < 2; mf++) {
#pragma unroll
        for (int nf = 0; nf < 2; nf++) {
#pragma unroll
            for (int h = 0; h < 2; h++) {
                int b  = mf*16 + (lane >> 2) + h * 8;
                int oo = o0 + wn*16 + nf*8 + (lane & 3) * 2;
                float v0 = (acc1[mf][nf][h*2]     + sgn * acc2[mf][nf][h*2])     * sc;
                float v1 = (acc1[mf][nf][h*2 + 1] + sgn * acc2[mf][nf][h*2 + 1]) * sc;
                __nv_bfloat16 hh, ll;
                size_t i0 = ((size_t)b * CH + oo) * NC + cidx;
                split_bf16(v0, hh, ll); g_oft_h[i0] = hh; g_oft_l[i0] = ll;
                size_t i1 = ((size_t)b * CH + oo + 1) * NC + cidx;
                split_bf16(v1, hh, ll); g_oft_h[i1] = hh; g_oft_l[i1] = ll;
            }
        }
    }
}

// ---------------------------------------------------------------------------
// Inverse DFT + LeakyReLU + residual. NEW: warp tile 64x64.
// 256 threads; block 128 rows x 256 t; warp grid 2x4; K=256 (4 chunks of 64).
// Halves smem-read bytes per MMA (256 -> 128 B). 192KB smem, 1 CTA/SM.
// ---------------------------------------------------------------------------
#define IV_AH 0
#define IV_AL 16384
#define IV_BH 32768
#define IV_BL 65536
#define IVBUF 98304
#define SMEM_INV (2*IVBUF)   // 192KB

__global__ void __launch_bounds__(256, 1) k_inv(const float* __restrict__ x,
                                                float* __restrict__ out) {
    extern __shared__ char sm[];
    uint32_t sb = smem_u32(sm);
    const int tid = threadIdx.x, lane = tid & 31, wid = tid >> 5;
    const int wr = wid & 1, wc = wid >> 1;      // 2 row x 4 t groups
    const int t0   = blockIdx.x * 256;
    const int row0 = blockIdx.y * 128;

    uint32_t offA[4], offB[4];
#pragma unroll
    for (int mf = 0; mf < 4; mf++)
        offA[mf] = (wr*64 + mf*16 + (lane & 15)) * 128 + (lane >> 4) * 16;
#pragma unroll
    for (int p = 0; p < 4; p++)
        offB[p] = (wc*64 + p*16 + ((lane >> 4) << 3) + (lane & 7)) * 128
                + ((lane >> 3) & 1) * 16;

    float acc[4][8][4];
#pragma unroll
    for (int i = 0; i < 4; i++)
#pragma unroll
        for (int j = 0; j < 8; j++)
#pragma unroll
            for (int q = 0; q < 4; q++) acc[i][j][q] = 0.0f;

#define INV_LOAD(dstb, kk) do {                                                   \
    _Pragma("unroll")                                                             \
    for (int j = 0; j < 8; j++) {                                                 \
        int f = tid + j * 256;                                                    \
        int plane = f >> 10, r = (f >> 3) & 127, cb = f & 7;                      \
        const __nv_bfloat16* src = (plane ? g_oft_l : g_oft_h)                    \
                                 + (size_t)(row0 + r) * NC + (kk) + cb * 8;       \
        CP16((dstb) + IV_AH + plane * 16384 + SW(r * 128 + cb * 16), src);        \
    }                                                                             \
    _Pragma("unroll")                                                             \
    for (int j = 0; j < 16; j++) {                                                \
        int f = tid + j * 256;                                                    \
        int plane = f >> 11, r = (f >> 3) & 255, cb = f & 7;                      \
        const __nv_bfloat16* src = (plane ? g_basis_l : g_basis_h)                \
                                 + (size_t)(t0 + r) * NC + (kk) + cb * 8;         \
        CP16((dstb) + IV_BH + plane * 32768 + SW(r * 128 + cb * 16), src);        \
    }                                                                             \
    CP_COMMIT();                                                                  \
} while (0)

    INV_LOAD(sb, 0);
    CP_WAIT0();
    __syncthreads();

    const int NCHUNK = NC / 64;
    for (int cc = 0; cc < NCHUNK; cc++) {
        uint32_t bb  = sb + (cc & 1) * IVBUF;
        uint32_t nbb = sb + ((cc + 1) & 1) * IVBUF;
        if (cc + 1 < NCHUNK) INV_LOAD(nbb, (cc + 1) * 64);
#pragma unroll
        for (int ks = 0; ks < 4; ks++) {
            uint32_t Ah[4][4], Bh[4][4];
#pragma unroll
            for (int mf = 0; mf < 4; mf++) LDSM4(Ah[mf], bb + IV_AH + SW(offA[mf] + ks * 32));
#pragma unroll
            for (int p = 0; p < 4; p++)    LDSM4(Bh[p],  bb + IV_BH + SW(offB[p] + ks * 32));
#pragma unroll
            for (int mf = 0; mf < 4; mf++)
#pragma unroll
                for (int nf = 0; nf < 8; nf++)
                    MMA4(acc[mf][nf], Ah[mf], Bh[nf>>1][(nf&1)*2], Bh[nf>>1][(nf&1)*2+1]);
            {
                uint32_t Bl[4][4];
#pragma unroll
                for (int p = 0; p < 4; p++) LDSM4(Bl[p], bb + IV_BL + SW(offB[p] + ks * 32));
#pragma unroll
                for (int mf = 0; mf < 4; mf++)
#pragma unroll
                    for (int nf = 0; nf < 8; nf++)
                        MMA4(acc[mf][nf], Ah[mf], Bl[nf>>1][(nf&1)*2], Bl[nf>>1][(nf&1)*2+1]);
            }
            {
                uint32_t Al[4][4];
#pragma unroll
                for (int mf = 0; mf < 4; mf++) LDSM4(Al[mf], bb + IV_AL + SW(offA[mf] + ks * 32));
#pragma unroll
                for (int mf = 0; mf < 4; mf++)
#pragma unroll
                    for (int nf = 0; nf < 8; nf++)
                        MMA4(acc[mf][nf], Al[mf], Bh[nf>>1][(nf&1)*2], Bh[nf>>1][(nf&1)*2+1]);
            }
        }
        CP_WAIT0();
        __syncthreads();
    }
#undef INV_LOAD
    // ---- epilogue: LeakyReLU + residual ----
#pragma unroll
    for (int mf = 0; mf < 4; mf++) {
        int row = row0 + wr*64 + mf*16 + (lane >> 2);
#pragma unroll
        for (int nf = 0; nf < 8; nf++) {
            int tc = t0 + wc*64 + nf*8 + (lane & 3) * 2;
#pragma unroll
            for (int h = 0; h < 2; h++) {
                size_t base = (size_t)(row + h * 8) * M_SIZE + tc;
                float2 xv = *(const float2*)&x[base];
                float v0 = acc[mf][nf][h*2], v1 = acc[mf][nf][h*2+1];
                float2 rv;
                rv.x = xv.x + (v0 >= 0.f ? v0 : 0.2f * v0);
                rv.y = xv.y + (v1 >= 0.f ? v1 : 0.2f * v1);
                *(float2*)&out[base] = rv;
            }
        }
    }
}

// ---------------------------------------------------------------------------
extern "C" void kernel_launch(void* const* d_in, const int* in_sizes, int n_in,
                              void* d_out, int out_size) {
    (void)in_sizes; (void)n_in; (void)out_size;
    const float*  x  = (const float*)d_in[0];
    const float2* w2 = (const float2*)d_in[1];
    float* out = (float*)d_out;

    cudaFuncSetAttribute(k_fwd,    cudaFuncAttributeMaxDynamicSharedMemorySize, SMEM_FWD);
    cudaFuncSetAttribute(k_inv,    cudaFuncAttributeMaxDynamicSharedMemorySize, SMEM_INV);
    cudaFuncSetAttribute(k_mixmma, cudaFuncAttributeMaxDynamicSharedMemorySize, SMEM_MIX);

    k_prep<<<8192, 256>>>(w2);
    k_fwd<<<dim3(NROWS / 128, NC / 128), 256, SMEM_FWD>>>(x);
    k_mixmma<<<dim3(NMODES, CH / 64), 256, SMEM_MIX>>>();
    k_inv<<<dim3(M_SIZE / 256, NROWS / 128), 256, SMEM_INV>>>(x, out);
}

// round 16
// speedup vs baseline: 1.3431x; 1.3431x over previous
#include <cuda_runtime.h>
#include <cuda_fp16.h>
#include <stdint.h>

#define M_SIZE 4096
#define NMODES 128
#define BATCH  32
#define CH     256
#define NROWS  (BATCH*CH)   // 8192
#define NC     (2*NMODES)   // 256

// ---------------- device scratch (allocation-free globals) ----------------
__device__ __half g_basis [(size_t)M_SIZE*NC];   // [t][c]  (inv B, single plane)
__device__ __half g_basisT[(size_t)NC*M_SIZE];   // [c][t]  (fwd B, single plane)
__device__ __half g_xT_h[(size_t)NC*NROWS];      // xft split planes [c][row]
__device__ __half g_xT_l[(size_t)NC*NROWS];
__device__ __half gWre[(size_t)NMODES*CH*CH];    // weight single planes [m][o][i]
__device__ __half gWim[(size_t)NMODES*CH*CH];
__device__ __half g_oft_h[(size_t)NROWS*NC];     // [row][c] scaled, split
__device__ __half g_oft_l[(size_t)NROWS*NC];

// ---------------- helpers ----------------
__device__ __forceinline__ uint32_t smem_u32(const void* p) {
    uint32_t a;
    asm("{ .reg .u64 t; cvta.to.shared.u64 t, %1; cvt.u32.u64 %0, t; }" : "=r"(a) : "l"(p));
    return a;
}
#define SW(o) ((uint32_t)(o) ^ ((((uint32_t)(o)) >> 3) & 0x70))

#define CP16(d, s)  asm volatile("cp.async.cg.shared.global [%0], [%1], 16;" :: "r"(d), "l"(s))
#define CP_COMMIT() asm volatile("cp.async.commit_group;")
#define CP_WAIT0()  asm volatile("cp.async.wait_group 0;")

#define LDSM4(R, addr) \
    asm volatile("ldmatrix.sync.aligned.m8n8.x4.shared.b16 {%0,%1,%2,%3}, [%4];" \
        : "=r"((R)[0]), "=r"((R)[1]), "=r"((R)[2]), "=r"((R)[3]) : "r"(addr))

#define MMA4(C, A, b0, b1) \
    asm volatile("mma.sync.aligned.m16n8k16.row.col.f32.f16.f16.f32 " \
        "{%0,%1,%2,%3},{%4,%5,%6,%7},{%8,%9},{%0,%1,%2,%3};" \
        : "+f"((C)[0]), "+f"((C)[1]), "+f"((C)[2]), "+f"((C)[3]) \
        : "r"((A)[0]), "r"((A)[1]), "r"((A)[2]), "r"((A)[3]), "r"(b0), "r"(b1))

__device__ __forceinline__ void split_f16(float v, __half& h, __half& l) {
    h = __float2half(v);
    l = __float2half(v - __half2float(h));
}
__device__ __forceinline__ uint2 pack4(__half a, __half b, __half c, __half d) {
    __half2 p = __halves2half2(a, b), q = __halves2half2(c, d);
    return make_uint2(*(uint32_t*)&p, *(uint32_t*)&q);
}

// ---------------------------------------------------------------------------
// Fused prep: basis_a (0..2047), basis_b (2048..4095), wtransp (4096..8191)
// Single fp16 planes for basis and W.
// ---------------------------------------------------------------------------
__global__ void __launch_bounds__(256) k_prep(const float2* __restrict__ w2) {
    __shared__ float2 s[64][33];
    const int b = blockIdx.x;
    const int tid = threadIdx.x;
    if (b < 2048) {
        int idx = b * 256 + tid;
        int t = idx >> 7, m = idx & 127;
        int r = (t * m) & (M_SIZE - 1);
        float sn, cs;
        sincospif((float)r * (1.0f / 2048.0f), &sn, &cs);
        __half2 v = __halves2half2(__float2half(cs), __float2half(-sn));
        *(__half2*)&g_basis[(size_t)t * NC + 2 * m] = v;
    } else if (b < 4096) {
        int idx = (b - 2048) * 256 + tid;
        int m = idx >> 12, t = idx & 4095;
        int r = (t * m) & (M_SIZE - 1);
        float sn, cs;
        sincospif((float)r * (1.0f / 2048.0f), &sn, &cs);
        g_basisT[(size_t)(2*m)   * M_SIZE + t] = __float2half(cs);
        g_basisT[(size_t)(2*m+1) * M_SIZE + t] = __float2half(-sn);
    } else {
        int lb = b - 4096;
        const int i0 = (lb & 3) * 64;
        const int m0 = ((lb >> 2) & 3) * 32;
        const int o  = lb >> 4;
#pragma unroll
        for (int j = 0; j < 8; j++) {
            int f = tid + j * 256;
            int ii = f >> 5, ml = f & 31;
            s[ii][ml] = w2[((size_t)o * CH + i0 + ii) * NMODES + m0 + ml];
        }
        __syncthreads();
#pragma unroll
        for (int j = 0; j < 2; j++) {
            int f = tid + j * 256;
            int ml = f >> 4, ig = (f & 15) * 4;
            float2 v0 = s[ig][ml], v1 = s[ig+1][ml], v2 = s[ig+2][ml], v3 = s[ig+3][ml];
            size_t dst = ((size_t)(m0 + ml) * CH + o) * CH + i0 + ig;
            *(uint2*)&gWre[dst] = pack4(__float2half(v0.x), __float2half(v1.x),
                                        __float2half(v2.x), __float2half(v3.x));
            *(uint2*)&gWim[dst] = pack4(__float2half(v0.y), __float2half(v1.y),
                                        __float2half(v2.y), __float2half(v3.y));
        }
    }
}

// ---------------------------------------------------------------------------
// Forward DFT: xT[c][row] = sum_k x[row][k]*basisT[c][k]
// 256 threads, 8 warps 2x4 (warp 64x32), block 128x128, K-chunk 64.
// A split fp16 hi/lo (inline convert), B single fp16 plane. 2 MMA products.
// ---------------------------------------------------------------------------
#define F_AH 0
#define F_AL 16384
#define F_B  32768
#define FBUF 49152
#define SMEM_FWD (2*FBUF)   // 96KB, 1 CTA/SM

__global__ void __launch_bounds__(256, 1) k_fwd(const float* __restrict__ x) {
    extern __shared__ char sm[];
    uint32_t sb = smem_u32(sm);
    const int tid = threadIdx.x, lane = tid & 31, wid = tid >> 5;
    const int wm = wid & 1, wn = wid >> 1;
    const int row0 = blockIdx.x * 128;
    const int c0   = blockIdx.y * 128;

    uint32_t offA[4], offB[2];
#pragma unroll
    for (int mf = 0; mf < 4; mf++)
        offA[mf] = (wm*64 + mf*16 + (lane & 15)) * 128 + (lane >> 4) * 16;
#pragma unroll
    for (int p = 0; p < 2; p++)
        offB[p] = (wn*32 + p*16 + ((lane >> 4) << 3) + (lane & 7)) * 128
                + ((lane >> 3) & 1) * 16;

    float acc[4][4][4];
#pragma unroll
    for (int i = 0; i < 4; i++)
#pragma unroll
        for (int j = 0; j < 4; j++)
#pragma unroll
            for (int q = 0; q < 4; q++) acc[i][j][q] = 0.0f;

    // ---- preload chunk 0 ----
    {
        const int k0 = 0;
#pragma unroll
        for (int j = 0; j < 4; j++) {            // B single plane: 128 x 8
            int f = tid + j * 256;
            int r = f >> 3, cb = f & 7;
            CP16(sb + F_B + SW(r * 128 + cb * 16),
                 g_basisT + (size_t)(c0 + r) * M_SIZE + k0 + cb * 8);
        }
        CP_COMMIT();
#pragma unroll
        for (int it = 0; it < 8; it++) {
            int f = tid + it * 256;
            int r = f >> 4, q = f & 15;
            float4 v = *(const float4*)&x[(size_t)(row0 + r) * M_SIZE + k0 + q * 4];
            __half h0,l0,h1,l1,h2,l2,h3,l3;
            split_f16(v.x,h0,l0); split_f16(v.y,h1,l1);
            split_f16(v.z,h2,l2); split_f16(v.w,h3,l3);
            uint32_t off = SW(r * 128 + q * 8);
            *(uint2*)(sm + F_AH + off) = pack4(h0,h1,h2,h3);
            *(uint2*)(sm + F_AL + off) = pack4(l0,l1,l2,l3);
        }
        CP_WAIT0();
    }
    __syncthreads();

    const int NCHUNK = M_SIZE / 64;
    for (int cc = 0; cc < NCHUNK; cc++) {
        uint32_t bb  = sb + (cc & 1) * FBUF;
        char*    nbp = sm + ((cc + 1) & 1) * FBUF;
        uint32_t nbb = sb + ((cc + 1) & 1) * FBUF;
        bool pf = (cc + 1 < NCHUNK);
        float4 va[8];
        int rpf[8], qpf[8];
        if (pf) {
            const int k1 = (cc + 1) * 64;
#pragma unroll
            for (int j = 0; j < 4; j++) {
                int f = tid + j * 256;
                int r = f >> 3, cb = f & 7;
                CP16(nbb + F_B + SW(r * 128 + cb * 16),
                     g_basisT + (size_t)(c0 + r) * M_SIZE + k1 + cb * 8);
            }
            CP_COMMIT();
#pragma unroll
            for (int it = 0; it < 8; it++) {
                int f = tid + it * 256;
                rpf[it] = f >> 4; qpf[it] = f & 15;
                va[it] = *(const float4*)&x[(size_t)(row0 + rpf[it]) * M_SIZE + k1 + qpf[it] * 4];
            }
        }
#pragma unroll
        for (int ks = 0; ks < 4; ks++) {
            uint32_t Ah[4][4], Al[4][4], Bf[2][4];
#pragma unroll
            for (int mf = 0; mf < 4; mf++) LDSM4(Ah[mf], bb + F_AH + SW(offA[mf] + ks * 32));
#pragma unroll
            for (int p = 0; p < 2; p++)    LDSM4(Bf[p],  bb + F_B  + SW(offB[p] + ks * 32));
#pragma unroll
            for (int mf = 0; mf < 4; mf++)
#pragma unroll
                for (int nf = 0; nf < 4; nf++)
                    MMA4(acc[mf][nf], Ah[mf], Bf[nf>>1][(nf&1)*2], Bf[nf>>1][(nf&1)*2+1]);
#pragma unroll
            for (int mf = 0; mf < 4; mf++) LDSM4(Al[mf], bb + F_AL + SW(offA[mf] + ks * 32));
#pragma unroll
            for (int mf = 0; mf < 4; mf++)
#pragma unroll
                for (int nf = 0; nf < 4; nf++)
                    MMA4(acc[mf][nf], Al[mf], Bf[nf>>1][(nf&1)*2], Bf[nf>>1][(nf&1)*2+1]);
        }
        if (pf) {
#pragma unroll
            for (int it = 0; it < 8; it++) {
                float4 v = va[it];
                __half h0,l0,h1,l1,h2,l2,h3,l3;
                split_f16(v.x,h0,l0); split_f16(v.y,h1,l1);
                split_f16(v.z,h2,l2); split_f16(v.w,h3,l3);
                uint32_t off = SW(rpf[it] * 128 + qpf[it] * 8);
                *(uint2*)(nbp + F_AH + off) = pack4(h0,h1,h2,h3);
                *(uint2*)(nbp + F_AL + off) = pack4(l0,l1,l2,l3);
            }
        }
        CP_WAIT0();
        __syncthreads();
    }

    // ---- epilogue: stage accs in smem, coalesced fp16 plane writes ----
    float* stage = (float*)sm;
#pragma unroll
    for (int mf = 0; mf < 4; mf++) {
        int lr = wm*64 + mf*16 + (lane >> 2);
#pragma unroll
        for (int nf = 0; nf < 4; nf++) {
            int lc = wn*32 + nf*8 + (lane & 3) * 2;
#pragma unroll
            for (int q = 0; q < 4; q++)
                stage[(lc + (q & 1)) * 132 + lr + (q >> 1) * 8] = acc[mf][nf][q];
        }
    }
    __syncthreads();
    {
        const int c  = tid >> 1;
        const int rh = tid & 1;
        const float* srow = stage + c * 132 + rh * 64;
        __half* dh = &g_xT_h[(size_t)(c0 + c) * NROWS + row0 + rh * 64];
        __half* dl = &g_xT_l[(size_t)(c0 + c) * NROWS + row0 + rh * 64];
#pragma unroll
        for (int i = 0; i < 64; i += 4) {
            __half h0,l0,h1,l1,h2,l2,h3,l3;
            split_f16(srow[i],   h0,l0); split_f16(srow[i+1], h1,l1);
            split_f16(srow[i+2], h2,l2); split_f16(srow[i+3], h3,l3);
            *(uint2*)&dh[i] = pack4(h0,h1,h2,h3);
            *(uint2*)&dl[i] = pack4(l0,l1,l2,l3);
        }
    }
}

// ---------------------------------------------------------------------------
// MMA mode mixing. CTA = (mode m, 64-wide o slice). M=32,N=64,K=256.
// A split fp16 (re_h,re_l,im_h,im_l), W single fp16 planes. 2 products/combo.
// ---------------------------------------------------------------------------
#define MX_REH 0
#define MX_REL 16384
#define MX_IMH 32768
#define MX_IML 49152
#define MW_BASE 65536
#define SMEM_MIX (MW_BASE + 16384)   // 80KB -> 2 CTAs/SM

__global__ void __launch_bounds__(256, 2) k_mixmma() {
    extern __shared__ char sm[];
    uint32_t sb = smem_u32(sm);
    const int tid = threadIdx.x, lane = tid & 31, wid = tid >> 5;
    const int wg = wid >> 2, wn = wid & 3;
    const int m  = blockIdx.x;
    const int o0 = blockIdx.y * 64;

#define MIX_LOADW(kk) do {                                                        \
    _Pragma("unroll")                                                             \
    for (int j = 0; j < 4; j++) {                                                 \
        int f = tid + j * 256;                                                    \
        int p = f >> 9, r = (f >> 3) & 63, cb = f & 7;                            \
        const __half* src = p ? gWim : gWre;                                      \
        CP16(sb + MW_BASE + p * 8192 + SW(r * 128 + cb * 16),                     \
             src + ((size_t)m * CH + o0 + r) * CH + (kk) + cb * 8);               \
    }                                                                             \
    CP_COMMIT();                                                                  \
} while (0)

    {
        const __half* srcs[4] = {
            g_xT_h + (size_t)(2 * m)     * NROWS,
            g_xT_l + (size_t)(2 * m)     * NROWS,
            g_xT_h + (size_t)(2 * m + 1) * NROWS,
            g_xT_l + (size_t)(2 * m + 1) * NROWS };
#pragma unroll
        for (int j = 0; j < 16; j++) {
            int f = tid + j * 256;
            int p = f >> 10, rem = f & 1023;
            int b = rem >> 5, cb32 = rem & 31;
            int chunk = cb32 >> 3, cb = cb32 & 7;
            CP16(sb + p * 16384 + chunk * 4096 + SW(b * 128 + cb * 16),
                 srcs[p] + (size_t)b * CH + cb32 * 8);
        }
        MIX_LOADW(0);
        CP_WAIT0();
    }
    __syncthreads();

    uint32_t offA[2], offB;
#pragma unroll
    for (int mf = 0; mf < 2; mf++)
        offA[mf] = (mf*16 + (lane & 15)) * 128 + (lane >> 4) * 16;
    offB = (wn*16 + ((lane >> 4) << 3) + (lane & 7)) * 128 + ((lane >> 3) & 1) * 16;

    const uint32_t b1 = wg ? 8192u : 0u;     // acc1: Wim : Wre
    const uint32_t b2 = wg ? 0u : 8192u;     // acc2: Wre : Wim

    float acc1[2][2][4], acc2[2][2][4];
#pragma unroll
    for (int i = 0; i < 2; i++)
#pragma unroll
        for (int j = 0; j < 2; j++)
#pragma unroll
            for (int q = 0; q < 4; q++) { acc1[i][j][q] = 0.0f; acc2[i][j][q] = 0.0f; }

    for (int cc = 0; cc < 4; cc++) {
        uint32_t wb = sb + MW_BASE;
#pragma unroll
        for (int ks = 0; ks < 4; ks++) {
#pragma unroll
            for (int combo = 0; combo < 2; combo++) {
                uint32_t ah = sb + (combo ? MX_IMH : MX_REH) + cc * 4096;
                uint32_t al = sb + (combo ? MX_IML : MX_REL) + cc * 4096;
                uint32_t bbx = wb + (combo ? b2 : b1);
                float (*acc)[2][4] = combo ? acc2 : acc1;
                uint32_t Ah[2][4], Al[2][4], Bf[4];
#pragma unroll
                for (int mf = 0; mf < 2; mf++) {
                    LDSM4(Ah[mf], ah + SW(offA[mf] + ks * 32));
                    LDSM4(Al[mf], al + SW(offA[mf] + ks * 32));
                }
                LDSM4(Bf, bbx + SW(offB + ks * 32));
#pragma unroll
                for (int mf = 0; mf < 2; mf++)
#pragma unroll
                    for (int nf = 0; nf < 2; nf++) {
                        MMA4(acc[mf][nf], Ah[mf], Bf[nf*2], Bf[nf*2+1]);
                        MMA4(acc[mf][nf], Al[mf], Bf[nf*2], Bf[nf*2+1]);
                    }
            }
        }
        __syncthreads();
        if (cc + 1 < 4) {
            MIX_LOADW((cc + 1) * 64);
            CP_WAIT0();
            __syncthreads();
        }
    }
#undef MIX_LOADW

    const float sgn = wg ? 1.0f : -1.0f;
    const float sc = (m == 0 ? 1.0f : 2.0f) * (1.0f / (float)M_SIZE);
    const int cidx = 2 * m + wg;
#pragma unroll
    for (int mf = 0; mf < 2; mf++) {
#pragma unroll
        for (int nf = 0; nf < 2; nf++) {
#pragma unroll
            for (int h = 0; h < 2; h++) {
                int b  = mf*16 + (lane >> 2) + h * 8;
                int oo = o0 + wn*16 + nf*8 + (lane & 3) * 2;
                float v0 = (acc1[mf][nf][h*2]     + sgn * acc2[mf][nf][h*2])     * sc;
                float v1 = (acc1[mf][nf][h*2 + 1] + sgn * acc2[mf][nf][h*2 + 1]) * sc;
                __half hh, ll;
                size_t i0 = ((size_t)b * CH + oo) * NC + cidx;
                split_f16(v0, hh, ll); g_oft_h[i0] = hh; g_oft_l[i0] = ll;
                size_t i1 = ((size_t)b * CH + oo + 1) * NC + cidx;
                split_f16(v1, hh, ll); g_oft_h[i1] = hh; g_oft_l[i1] = ll;
            }
        }
    }
}

// ---------------------------------------------------------------------------
// Inverse DFT + LeakyReLU + residual.
// 256 threads; block 64 rows x 128 t; warp grid 2x4, warp tile 32x32.
// A split fp16 hi/lo, B single fp16 plane. 2 MMA products.
// ---------------------------------------------------------------------------
#define P_AH 0
#define P_AL 8192
#define P_B  16384
#define BUFB 32768
#define SMEM_INV (2*BUFB)   // 64KB -> 2 CTAs/SM

__global__ void __launch_bounds__(256, 2) k_inv(const float* __restrict__ x,
                                                float* __restrict__ out) {
    extern __shared__ char sm[];
    uint32_t sb = smem_u32(sm);
    const int tid = threadIdx.x, lane = tid & 31, wid = tid >> 5;
    const int wr = wid & 1, wc = wid >> 1;
    const int t0   = blockIdx.x * 128;
    const int row0 = blockIdx.y * 64;

    uint32_t offA[2], offB[2];
#pragma unroll
    for (int mf = 0; mf < 2; mf++)
        offA[mf] = (wr*32 + mf*16 + (lane & 15)) * 128 + (lane >> 4) * 16;
#pragma unroll
    for (int p = 0; p < 2; p++)
        offB[p] = (wc*32 + p*16 + ((lane >> 4) << 3) + (lane & 7)) * 128
                + ((lane >> 3) & 1) * 16;

    float acc[2][4][4];
#pragma unroll
    for (int i = 0; i < 2; i++)
#pragma unroll
        for (int j = 0; j < 4; j++)
#pragma unroll
            for (int q = 0; q < 4; q++) acc[i][j][q] = 0.0f;

#define INV_LOAD(dstb, kk) do {                                                   \
    _Pragma("unroll")                                                             \
    for (int j = 0; j < 4; j++) {                                                 \
        int f = tid + j * 256;                                                    \
        int plane = f >> 9, r = (f >> 3) & 63, cb = f & 7;                        \
        const __half* src = (plane ? g_oft_l : g_oft_h)                           \
                          + (size_t)(row0 + r) * NC + (kk) + cb * 8;              \
        CP16((dstb) + P_AH + plane * 8192 + SW(r * 128 + cb * 16), src);          \
    }                                                                             \
    _Pragma("unroll")                                                             \
    for (int j = 0; j < 4; j++) {                                                 \
        int f = tid + j * 256;                                                    \
        int r = f >> 3, cb = f & 7;                                               \
        CP16((dstb) + P_B + SW(r * 128 + cb * 16),                                \
             g_basis + (size_t)(t0 + r) * NC + (kk) + cb * 8);                    \
    }                                                                             \
    CP_COMMIT();                                                                  \
} while (0)

    INV_LOAD(sb, 0);
    CP_WAIT0();
    __syncthreads();

    const int NCHUNK = NC / 64;
    for (int cc = 0; cc < NCHUNK; cc++) {
        uint32_t bb  = sb + (cc & 1) * BUFB;
        uint32_t nbb = sb + ((cc + 1) & 1) * BUFB;
        if (cc + 1 < NCHUNK) INV_LOAD(nbb, (cc + 1) * 64);
#pragma unroll
        for (int ks = 0; ks < 4; ks++) {
            uint32_t Ah[2][4], Al[2][4], Bf[2][4];
#pragma unroll
            for (int mf = 0; mf < 2; mf++) LDSM4(Ah[mf], bb + P_AH + SW(offA[mf] + ks * 32));
#pragma unroll
            for (int p = 0; p < 2; p++)    LDSM4(Bf[p],  bb + P_B  + SW(offB[p] + ks * 32));
#pragma unroll
            for (int mf = 0; mf < 2; mf++)
#pragma unroll
                for (int nf = 0; nf < 4; nf++)
                    MMA4(acc[mf][nf], Ah[mf], Bf[nf>>1][(nf&1)*2], Bf[nf>>1][(nf&1)*2+1]);
#pragma unroll
            for (int mf = 0; mf < 2; mf++) LDSM4(Al[mf], bb + P_AL + SW(offA[mf] + ks * 32));
#pragma unroll
            for (int mf = 0; mf < 2; mf++)
#pragma unroll
                for (int nf = 0; nf < 4; nf++)
                    MMA4(acc[mf][nf], Al[mf], Bf[nf>>1][(nf&1)*2], Bf[nf>>1][(nf&1)*2+1]);
        }
        CP_WAIT0();
        __syncthreads();
    }
#undef INV_LOAD
#pragma unroll
    for (int mf = 0; mf < 2; mf++) {
        int row = row0 + wr*32 + mf*16 + (lane >> 2);
#pragma unroll
        for (int nf = 0; nf < 4; nf++) {
            int tc = t0 + wc*32 + nf*8 + (lane & 3) * 2;
#pragma unroll
            for (int h = 0; h < 2; h++) {
                size_t base = (size_t)(row + h * 8) * M_SIZE + tc;
                float2 xv = *(const float2*)&x[base];
                float v0 = acc[mf][nf][h*2], v1 = acc[mf][nf][h*2+1];
                float2 rv;
                rv.x = xv.x + (v0 >= 0.f ? v0 : 0.2f * v0);
                rv.y = xv.y + (v1 >= 0.f ? v1 : 0.2f * v1);
                *(float2*)&out[base] = rv;
            }
        }
    }
}

// ---------------------------------------------------------------------------
extern "C" void kernel_launch(void* const* d_in, const int* in_sizes, int n_in,
                              void* d_out, int out_size) {
    (void)in_sizes; (void)n_in; (void)out_size;
    const float*  x  = (const float*)d_in[0];
    const float2* w2 = (const float2*)d_in[1];
    float* out = (float*)d_out;

    cudaFuncSetAttribute(k_fwd,    cudaFuncAttributeMaxDynamicSharedMemorySize, SMEM_FWD);
    cudaFuncSetAttribute(k_inv,    cudaFuncAttributeMaxDynamicSharedMemorySize, SMEM_INV);
    cudaFuncSetAttribute(k_mixmma, cudaFuncAttributeMaxDynamicSharedMemorySize, SMEM_MIX);

    k_prep<<<8192, 256>>>(w2);
    k_fwd<<<dim3(NROWS / 128, NC / 128), 256, SMEM_FWD>>>(x);
    k_mixmma<<<dim3(NMODES, CH / 64), 256, SMEM_MIX>>>();
    k_inv<<<dim3(M_SIZE / 128, NROWS / 64), 256, SMEM_INV>>>(x, out);
}